// round 11
// baseline (speedup 1.0000x reference)
#include <cuda_runtime.h>
#include <math.h>

#define BB 4
#define NN 8192
#define SS 2048
#define KK 32
#define DD 29
#define MM (BB*SS*KK)
#define NEWXYZ_SIZE (BB*3*SS)

__device__ float g_X[32 * MM];
__device__ float g_P[64 * MM];
__device__ float g_U[64 * MM];
__device__ float g_V[64 * MM];
__device__ float g_A[64 * MM];
__device__ int    g_fidx[BB * SS];
__device__ double g_stats[5 * 128];
__device__ float  g_scale[5 * 64];
__device__ float  g_shift[5 * 64];

// ---------- packed f32x2 helpers ----------
__device__ __forceinline__ unsigned long long pack2(float lo, float hi) {
    unsigned long long r;
    asm("mov.b64 %0,{%1,%2};" : "=l"(r) : "f"(lo), "f"(hi));
    return r;
}
__device__ __forceinline__ void unpack2(unsigned long long v, float& lo, float& hi) {
    asm("mov.b64 {%0,%1},%2;" : "=f"(lo), "=f"(hi) : "l"(v));
}
__device__ __forceinline__ unsigned long long add2(unsigned long long a, unsigned long long b) {
    unsigned long long r;
    asm("add.rn.f32x2 %0,%1,%2;" : "=l"(r) : "l"(a), "l"(b));
    return r;
}
__device__ __forceinline__ unsigned long long mul2_(unsigned long long a, unsigned long long b) {
    unsigned long long r;
    asm("mul.rn.f32x2 %0,%1,%2;" : "=l"(r) : "l"(a), "l"(b));
    return r;
}
__device__ __forceinline__ void fma2(unsigned long long& acc,
                                     unsigned long long a, unsigned long long bv) {
    asm("fma.rn.f32x2 %0, %1, %2, %0;" : "+l"(acc) : "l"(a), "l"(bv));
}

__global__ void zero_stats_kernel() {
    int t = threadIdx.x;
    for (int i = t; i < 5 * 128; i += 64) g_stats[i] = 0.0;
}

// ---------- FPS: 4 blocks x 256 threads; xyz staged in smem; u64-atom argmax ----------
__global__ void __launch_bounds__(256) fps_kernel(const float* __restrict__ xyz) {
    extern __shared__ float fsm[];
    float* sx = fsm;
    float* sy = fsm + NN;
    float* sz = fsm + 2 * NN;
    unsigned long long* red = (unsigned long long*)(fsm + 3 * NN);  // 3 slots

    int b = blockIdx.x;
    const float* Xp = xyz + b * 3 * NN;
    const float* Yp = Xp + NN;
    const float* Zp = Xp + 2 * NN;
    int tid = threadIdx.x, lane = tid & 31;

    for (int i = tid; i < NN; i += 256) {
        sx[i] = Xp[i]; sy[i] = Yp[i]; sz[i] = Zp[i];
    }
    if (tid < 3) red[tid] = 0ull;

    unsigned long long Px[16], Py[16], Pz[16];
    float dist[32];
#pragma unroll
    for (int q = 0; q < 16; q++) {
        int n0 = (2 * q) * 256 + tid, n1 = n0 + 256;
        Px[q] = pack2(Xp[n0], Xp[n1]);
        Py[q] = pack2(Yp[n0], Yp[n1]);
        Pz[q] = pack2(Zp[n0], Zp[n1]);
        dist[2 * q] = 1e10f; dist[2 * q + 1] = 1e10f;
    }
    __syncthreads();

    int far = 0;
    int p = 0;           // rotating slot
    for (int it = 0; it < SS; it++) {
        if (tid == 0) g_fidx[b * SS + it] = far;
        float cx = sx[far], cy = sy[far], cz = sz[far];
        unsigned long long nc_x = pack2(-cx, -cx);
        unsigned long long nc_y = pack2(-cy, -cy);
        unsigned long long nc_z = pack2(-cz, -cz);

        unsigned bbits = 0u, bidx = 0u;
#pragma unroll
        for (int q = 0; q < 16; q++) {
            unsigned long long ax = add2(Px[q], nc_x);
            unsigned long long ay = add2(Py[q], nc_y);
            unsigned long long az = add2(Pz[q], nc_z);
            unsigned long long s  = add2(mul2_(ax, ax), mul2_(ay, ay));
            unsigned long long dd = add2(s, mul2_(az, az));
            float d0, d1; unpack2(dd, d0, d1);
            float nd0 = fminf(dist[2 * q], d0); dist[2 * q] = nd0;
            float nd1 = fminf(dist[2 * q + 1], d1); dist[2 * q + 1] = nd1;
            unsigned u0 = __float_as_uint(nd0);
            if (u0 > bbits) { bbits = u0; bidx = (unsigned)((2 * q) * 256 + tid); }
            unsigned u1 = __float_as_uint(nd1);
            if (u1 > bbits) { bbits = u1; bidx = (unsigned)((2 * q + 1) * 256 + tid); }
        }
        // warp argmax (first-max tie break)
        unsigned wmax = __reduce_max_sync(0xffffffffu, bbits);
        unsigned cand = (bbits == wmax) ? bidx : 0xffffffffu;
        unsigned wmin = __reduce_min_sync(0xffffffffu, cand);
        if (lane == 0) {
            unsigned long long pk = ((unsigned long long)wmax << 32)
                                  | (unsigned long long)(0xffffffffu - wmin);
            atomicMax(&red[p], pk);
        }
        __syncthreads();                       // drains atoms; orders resets
        unsigned long long pk = red[p];
        far = (int)(0xffffffffu - (unsigned)(pk & 0xffffffffull));
        // reset the slot that will be atom-written two barriers from now
        if (tid == 0) { int pr = p + 2; if (pr >= 3) pr -= 3; red[pr] = 0ull; }
        p = (p + 1 == 3) ? 0 : p + 1;
    }
}

// ---------- ball query + gather ----------
__global__ void __launch_bounds__(256) ballgather_kernel(
    const float* __restrict__ xyz, const float* __restrict__ points,
    float* __restrict__ out)
{
    __shared__ int snb[8][32];
    int tid = threadIdx.x, lane = tid & 31, w = tid >> 5;
    int cid = blockIdx.x * 8 + w;
    int b = cid >> 11, s = cid & 2047;

    const float* Xp = xyz + b * 3 * NN;
    const float* Yp = Xp + NN;
    const float* Zp = Xp + 2 * NN;

    int fi = g_fidx[b * SS + s];
    float cx = __ldg(Xp + fi), cy = __ldg(Yp + fi), cz = __ldg(Zp + fi);
    float cn = __fadd_rn(__fadd_rn(__fmul_rn(cx,cx), __fmul_rn(cy,cy)), __fmul_rn(cz,cz));
    if (lane == 0) out[b * 3 * SS + 0 * SS + s] = cx;
    if (lane == 1) out[b * 3 * SS + 1 * SS + s] = cy;
    if (lane == 2) out[b * 3 * SS + 2 * SS + s] = cz;

    const float R2 = 0.01f;
    int cnt = 0;
    for (int base = 0; base < NN; base += 32) {
        int j = base + lane;
        float pxv = __ldg(Xp + j), pyv = __ldg(Yp + j), pzv = __ldg(Zp + j);
        float pn  = __fadd_rn(__fadd_rn(__fmul_rn(pxv,pxv), __fmul_rn(pyv,pyv)), __fmul_rn(pzv,pzv));
        float dot = __fadd_rn(__fadd_rn(__fmul_rn(cx,pxv), __fmul_rn(cy,pyv)), __fmul_rn(cz,pzv));
        float sqr = __fsub_rn(__fadd_rn(cn, pn), __fmul_rn(2.0f, dot));
        bool in = (sqr <= R2);
        unsigned mask = __ballot_sync(0xffffffffu, in);
        int pre = __popc(mask & ((1u << lane) - 1u));
        int slot = cnt + pre;
        if (in && slot < 32) snb[w][slot] = j;
        cnt += __popc(mask);
        if (cnt >= 32) break;
    }
    __syncwarp();
    int j0 = snb[w][0];
    if (lane >= cnt) snb[w][lane] = j0;
    __syncwarp();
    int j = snb[w][lane];

    size_t mbase = (size_t)cid * 32 + lane;
    float gx = __ldg(Xp + j), gy = __ldg(Yp + j), gz = __ldg(Zp + j);
    g_X[(size_t)0 * MM + mbase] = __fsub_rn(gx, cx);
    g_X[(size_t)1 * MM + mbase] = __fsub_rn(gy, cy);
    g_X[(size_t)2 * MM + mbase] = __fsub_rn(gz, cz);
    const float* pb = points + (size_t)b * DD * NN;
    for (int d = 0; d < DD; d++)
        g_X[(size_t)(3 + d) * MM + mbase] = __ldg(pb + d * NN + j);
}

// ---------- fused conv: 256 threads, 4 rows x 4 col-pairs per thread ----------
// MODE 0: in = A ; MODE 1: in = relu(scA*A+shA) ;
// MODE 2: in = relu(scA*A+shA + relu(scB*B2+shB)), also stored to actOut.
template<int CINt, int MODE>
__global__ void __launch_bounds__(256) conv_kernel(
    const float* __restrict__ W,
    const float* __restrict__ A, const float* __restrict__ B2,
    const float* __restrict__ scA, const float* __restrict__ shA,
    const float* __restrict__ scB, const float* __restrict__ shB,
    float* __restrict__ outp, float* __restrict__ actOut,
    double* __restrict__ stS, double* __restrict__ stQ)
{
    extern __shared__ float smem[];
    float* Ws = smem;               // [k][o] : CINt*64 floats
    float* Xs = smem + CINt * 64;   // [k][col] : CINt*128 floats
    int tid = threadIdx.x;
    int m0 = blockIdx.x * 128;

    for (int i = tid; i < 64 * CINt; i += 256) {
        int o = i & 63, k = i >> 6;
        Ws[k * 64 + o] = __ldg(W + o * CINt + k);
    }
    for (int i = tid; i < CINt * 32; i += 256) {
        int k = i >> 5, c = (i & 31) << 2;
        float4 v = *(const float4*)(A + (size_t)k * MM + m0 + c);
        if (MODE == 1) {
            float sc = scA[k], sh = shA[k];
            v.x = fmaxf(fmaf(sc, v.x, sh), 0.f);
            v.y = fmaxf(fmaf(sc, v.y, sh), 0.f);
            v.z = fmaxf(fmaf(sc, v.z, sh), 0.f);
            v.w = fmaxf(fmaf(sc, v.w, sh), 0.f);
        } else if (MODE == 2) {
            float sc = scA[k], sh = shA[k];
            float sb2 = scB[k], s2 = shB[k];
            float4 u = *(const float4*)(B2 + (size_t)k * MM + m0 + c);
            v.x = fmaxf(fmaf(sc, v.x, sh) + fmaxf(fmaf(sb2, u.x, s2), 0.f), 0.f);
            v.y = fmaxf(fmaf(sc, v.y, sh) + fmaxf(fmaf(sb2, u.y, s2), 0.f), 0.f);
            v.z = fmaxf(fmaf(sc, v.z, sh) + fmaxf(fmaf(sb2, u.z, s2), 0.f), 0.f);
            v.w = fmaxf(fmaf(sc, v.w, sh) + fmaxf(fmaf(sb2, u.w, s2), 0.f), 0.f);
            *(float4*)(actOut + (size_t)k * MM + m0 + c) = v;
        }
        *(float4*)(Xs + k * 128 + c) = v;
    }
    __syncthreads();

    int tc = tid & 15, tr = tid >> 4;    // tc: 4 col-pairs (j*16+tc), tr: 4 rows (tr*4+r)
    unsigned long long acc[4][4];
#pragma unroll
    for (int r = 0; r < 4; r++)
#pragma unroll
        for (int j = 0; j < 4; j++) acc[r][j] = 0ull;

    const unsigned long long* Xq = (const unsigned long long*)Xs;
#pragma unroll 4
    for (int k = 0; k < CINt; k++) {
        float4 wv = *(const float4*)(Ws + k * 64 + tr * 4);   // LDS.128, 2 addrs/warp
        unsigned long long w0 = pack2(wv.x, wv.x);
        unsigned long long w1 = pack2(wv.y, wv.y);
        unsigned long long w2 = pack2(wv.z, wv.z);
        unsigned long long w3 = pack2(wv.w, wv.w);
        unsigned long long x[4];
#pragma unroll
        for (int j = 0; j < 4; j++) x[j] = Xq[k * 64 + j * 16 + tc];  // 128B wavefronts
#pragma unroll
        for (int j = 0; j < 4; j++) {
            fma2(acc[0][j], w0, x[j]);
            fma2(acc[1][j], w1, x[j]);
            fma2(acc[2][j], w2, x[j]);
            fma2(acc[3][j], w3, x[j]);
        }
    }

#pragma unroll
    for (int r = 0; r < 4; r++) {
        int o = tr * 4 + r;
        unsigned long long* orow = (unsigned long long*)(outp + (size_t)o * MM + m0);
        float s = 0.f, sq = 0.f;
#pragma unroll
        for (int j = 0; j < 4; j++) {
            orow[j * 16 + tc] = acc[r][j];
            float f0, f1; unpack2(acc[r][j], f0, f1);
            s += f0 + f1; sq += f0 * f0 + f1 * f1;
        }
#pragma unroll
        for (int off = 8; off > 0; off >>= 1) {   // reduce across tc (low 4 lane bits)
            s  += __shfl_xor_sync(0xffffffffu, s, off);
            sq += __shfl_xor_sync(0xffffffffu, sq, off);
        }
        if (tc == 0) {
            atomicAdd(stS + o, (double)s);
            atomicAdd(stQ + o, (double)sq);
        }
    }
}

__global__ void bn_finalize_kernel(int bnIdx, const float* __restrict__ g,
                                   const float* __restrict__ b)
{
    int c = threadIdx.x;
    double sum = g_stats[bnIdx * 128 + c];
    double sq  = g_stats[bnIdx * 128 + 64 + c];
    double mean = sum * (1.0 / (double)MM);
    double var  = sq * (1.0 / (double)MM) - mean * mean;
    double inv  = 1.0 / sqrt(var + 1e-5);
    double sc   = (double)g[c] * inv;
    g_scale[bnIdx * 64 + c] = (float)sc;
    g_shift[bnIdx * 64 + c] = (float)((double)b[c] - mean * sc);
}

__global__ void __launch_bounds__(256) finalmax_kernel(float* __restrict__ out) {
    int gid = blockIdx.x * 256 + threadIdx.x;  // b*131072 + o*2048 + s
    int b = gid >> 17;
    int o = (gid >> 11) & 63;
    int s = gid & 2047;
    size_t m = (size_t)(b * SS + s) * KK;
    const float* vp = g_V + (size_t)o * MM + m;
    const float* ap = g_A + (size_t)o * MM + m;
    float sc = g_scale[4 * 64 + o], sh = g_shift[4 * 64 + o];
    float mx = 0.f;
#pragma unroll
    for (int kk = 0; kk < 8; kk++) {
        float4 v = *(const float4*)(vp + kk * 4);
        float4 a = *(const float4*)(ap + kk * 4);
        mx = fmaxf(mx, fmaxf(fmaf(sc, v.x, sh) + a.x, 0.f));
        mx = fmaxf(mx, fmaxf(fmaf(sc, v.y, sh) + a.y, 0.f));
        mx = fmaxf(mx, fmaxf(fmaf(sc, v.z, sh) + a.z, 0.f));
        mx = fmaxf(mx, fmaxf(fmaf(sc, v.w, sh) + a.w, 0.f));
    }
    out[NEWXYZ_SIZE + gid] = mx;
}

extern "C" void kernel_launch(void* const* d_in, const int* in_sizes, int n_in,
                              void* d_out, int out_size)
{
    const float* xyz    = (const float*)d_in[0];
    const float* points = (const float*)d_in[1];
    const float* proj_w = (const float*)d_in[2];
    const float* proj_g = (const float*)d_in[3];
    const float* proj_b = (const float*)d_in[4];
    const float* w1     = (const float*)d_in[5];
    const float* g1     = (const float*)d_in[6];
    const float* b1     = (const float*)d_in[7];
    const float* w2     = (const float*)d_in[8];
    const float* g2     = (const float*)d_in[9];
    const float* b2     = (const float*)d_in[10];
    float* out = (float*)d_out;

    float *pX, *pP, *pU, *pV, *pA, *pSc, *pSh;
    double* pSt;
    cudaGetSymbolAddress((void**)&pX, g_X);
    cudaGetSymbolAddress((void**)&pP, g_P);
    cudaGetSymbolAddress((void**)&pU, g_U);
    cudaGetSymbolAddress((void**)&pV, g_V);
    cudaGetSymbolAddress((void**)&pA, g_A);
    cudaGetSymbolAddress((void**)&pSt, g_stats);
    cudaGetSymbolAddress((void**)&pSc, g_scale);
    cudaGetSymbolAddress((void**)&pSh, g_shift);

    const int FPS_SMEM = 3 * NN * 4 + 32;   // 96 KB + red slots
    cudaFuncSetAttribute((const void*)fps_kernel,
                         cudaFuncAttributeMaxDynamicSharedMemorySize, FPS_SMEM);
    cudaFuncSetAttribute((const void*)conv_kernel<32,0>,
                         cudaFuncAttributeMaxDynamicSharedMemorySize, 49152);
    cudaFuncSetAttribute((const void*)conv_kernel<64,1>,
                         cudaFuncAttributeMaxDynamicSharedMemorySize, 49152);
    cudaFuncSetAttribute((const void*)conv_kernel<64,2>,
                         cudaFuncAttributeMaxDynamicSharedMemorySize, 49152);

    zero_stats_kernel<<<1, 64>>>();
    fps_kernel<<<BB, 256, FPS_SMEM>>>(xyz);
    ballgather_kernel<<<(BB * SS) / 8, 256>>>(xyz, points, out);

    // proj conv: P = proj_w * X (raw), stats bn0
    conv_kernel<32,0><<<MM/128, 256, 32*64*4 + 32*128*4>>>(proj_w, pX, nullptr,
        nullptr, nullptr, nullptr, nullptr, pP, nullptr, pSt + 0, pSt + 64);
    bn_finalize_kernel<<<1, 64>>>(0, proj_g, proj_b);

    // depth 0: U = w1[0] * relu(bn0(P)), stats bn1
    conv_kernel<64,1><<<MM/128, 256, 64*64*4 + 64*128*4>>>(w1, pP, nullptr,
        pSc + 0, pSh + 0, nullptr, nullptr, pU, nullptr, pSt + 128, pSt + 192);
    bn_finalize_kernel<<<1, 64>>>(1, g1, b1);

    // V = w2[0] * relu(bn1(U)), stats bn2
    conv_kernel<64,1><<<MM/128, 256, 64*64*4 + 64*128*4>>>(w2, pU, nullptr,
        pSc + 64, pSh + 64, nullptr, nullptr, pV, nullptr, pSt + 256, pSt + 320);
    bn_finalize_kernel<<<1, 64>>>(2, g2, b2);

    // depth 1: x1 = relu(bn2(V) + relu(bn0(P))) -> g_A ; U = w1[1] * x1, stats bn3
    conv_kernel<64,2><<<MM/128, 256, 64*64*4 + 64*128*4>>>(w1 + 64*64, pV, pP,
        pSc + 128, pSh + 128, pSc + 0, pSh + 0, pU, pA, pSt + 384, pSt + 448);
    bn_finalize_kernel<<<1, 64>>>(3, g1 + 64, b1 + 64);

    // V = w2[1] * relu(bn3(U)), stats bn4
    conv_kernel<64,1><<<MM/128, 256, 64*64*4 + 64*128*4>>>(w2 + 64*64, pU, nullptr,
        pSc + 192, pSh + 192, nullptr, nullptr, pV, nullptr, pSt + 512, pSt + 576);
    bn_finalize_kernel<<<1, 64>>>(4, g2 + 64, b2 + 64);

    // feat = max_k relu(bn4(V) + x1)
    finalmax_kernel<<<(BB * 64 * SS) / 256, 256>>>(out);
}

// round 12
// speedup vs baseline: 1.1900x; 1.1900x over previous
#include <cuda_runtime.h>
#include <math.h>

#define BB 4
#define NN 8192
#define SS 2048
#define KK 32
#define DD 29
#define MM (BB*SS*KK)
#define NEWXYZ_SIZE (BB*3*SS)

__device__ float g_X[32 * MM];
__device__ float g_P[64 * MM];
__device__ float g_U[64 * MM];
__device__ float g_V[64 * MM];
__device__ float g_A[64 * MM];
__device__ int    g_fidx[BB * SS];
__device__ double g_stats[5 * 128];
__device__ float  g_scale[5 * 64];
__device__ float  g_shift[5 * 64];

// ---------- packed f32x2 helpers ----------
__device__ __forceinline__ unsigned long long pack2(float lo, float hi) {
    unsigned long long r;
    asm("mov.b64 %0,{%1,%2};" : "=l"(r) : "f"(lo), "f"(hi));
    return r;
}
__device__ __forceinline__ void unpack2(unsigned long long v, float& lo, float& hi) {
    asm("mov.b64 {%0,%1},%2;" : "=f"(lo), "=f"(hi) : "l"(v));
}
__device__ __forceinline__ unsigned long long add2(unsigned long long a, unsigned long long b) {
    unsigned long long r;
    asm("add.rn.f32x2 %0,%1,%2;" : "=l"(r) : "l"(a), "l"(b));
    return r;
}
__device__ __forceinline__ unsigned long long mul2_(unsigned long long a, unsigned long long b) {
    unsigned long long r;
    asm("mul.rn.f32x2 %0,%1,%2;" : "=l"(r) : "l"(a), "l"(b));
    return r;
}
__device__ __forceinline__ void fma2(unsigned long long& acc,
                                     unsigned long long a, unsigned long long bv) {
    asm("fma.rn.f32x2 %0, %1, %2, %0;" : "+l"(acc) : "l"(a), "l"(bv));
}

__global__ void zero_stats_kernel() {
    int t = threadIdx.x;
    for (int i = t; i < 5 * 128; i += 64) g_stats[i] = 0.0;
}

// ---------- FPS: 4 blocks x 256 threads; centroid from smem; two-stage redux ----------
__global__ void __launch_bounds__(256) fps_kernel(const float* __restrict__ xyz) {
    extern __shared__ float fsm[];
    float* sx = fsm;
    float* sy = fsm + NN;
    float* sz = fsm + 2 * NN;
    unsigned* sb = (unsigned*)(fsm + 3 * NN);   // [2][8]
    unsigned* si = sb + 16;                      // [2][8]

    int b = blockIdx.x;
    const float* Xp = xyz + b * 3 * NN;
    const float* Yp = Xp + NN;
    const float* Zp = Xp + 2 * NN;
    int tid = threadIdx.x, lane = tid & 31, wid = tid >> 5;

    unsigned long long Px[16], Py[16], Pz[16];
    float dist[32];
#pragma unroll
    for (int q = 0; q < 16; q++) {
        int n0 = (2 * q) * 256 + tid, n1 = n0 + 256;
        float x0 = Xp[n0], x1 = Xp[n1];
        float y0 = Yp[n0], y1 = Yp[n1];
        float z0 = Zp[n0], z1 = Zp[n1];
        Px[q] = pack2(x0, x1);
        Py[q] = pack2(y0, y1);
        Pz[q] = pack2(z0, z1);
        sx[n0] = x0; sx[n1] = x1;
        sy[n0] = y0; sy[n1] = y1;
        sz[n0] = z0; sz[n1] = z1;
        dist[2 * q] = 1e10f; dist[2 * q + 1] = 1e10f;
    }
    __syncthreads();

    int far = 0;
    for (int it = 0; it < SS; it++) {
        if (tid == 0) g_fidx[b * SS + it] = far;
        float cx = sx[far], cy = sy[far], cz = sz[far];   // LDS broadcast, ~29 cyc
        unsigned long long nc_x = pack2(-cx, -cx);
        unsigned long long nc_y = pack2(-cy, -cy);
        unsigned long long nc_z = pack2(-cz, -cz);

        unsigned bbits = 0u, bidx = 0u;
#pragma unroll
        for (int q = 0; q < 16; q++) {
            unsigned long long ax = add2(Px[q], nc_x);
            unsigned long long ay = add2(Py[q], nc_y);
            unsigned long long az = add2(Pz[q], nc_z);
            unsigned long long s  = add2(mul2_(ax, ax), mul2_(ay, ay));
            unsigned long long dd = add2(s, mul2_(az, az));
            float d0, d1; unpack2(dd, d0, d1);
            float nd0 = fminf(dist[2 * q], d0); dist[2 * q] = nd0;
            float nd1 = fminf(dist[2 * q + 1], d1); dist[2 * q + 1] = nd1;
            unsigned u0 = __float_as_uint(nd0);
            if (u0 > bbits) { bbits = u0; bidx = (unsigned)((2 * q) * 256 + tid); }
            unsigned u1 = __float_as_uint(nd1);
            if (u1 > bbits) { bbits = u1; bidx = (unsigned)((2 * q + 1) * 256 + tid); }
        }
        // warp argmax (first-max tie break)
        unsigned wmax = __reduce_max_sync(0xffffffffu, bbits);
        unsigned cand = (bbits == wmax) ? bidx : 0xffffffffu;
        unsigned wmin = __reduce_min_sync(0xffffffffu, cand);
        int p = it & 1;
        if (lane == 0) { sb[p * 8 + wid] = wmax; si[p * 8 + wid] = wmin; }
        __syncthreads();
        unsigned vb = (lane < 8) ? sb[p * 8 + lane] : 0u;
        unsigned vi = (lane < 8) ? si[p * 8 + lane] : 0xffffffffu;
        unsigned gmax = __reduce_max_sync(0xffffffffu, vb);
        unsigned c2 = (vb == gmax) ? vi : 0xffffffffu;
        far = (int)__reduce_min_sync(0xffffffffu, c2);
    }
}

// ---------- ball query + gather ----------
__global__ void __launch_bounds__(256) ballgather_kernel(
    const float* __restrict__ xyz, const float* __restrict__ points,
    float* __restrict__ out)
{
    __shared__ int snb[8][32];
    int tid = threadIdx.x, lane = tid & 31, w = tid >> 5;
    int cid = blockIdx.x * 8 + w;
    int b = cid >> 11, s = cid & 2047;

    const float* Xp = xyz + b * 3 * NN;
    const float* Yp = Xp + NN;
    const float* Zp = Xp + 2 * NN;

    int fi = g_fidx[b * SS + s];
    float cx = __ldg(Xp + fi), cy = __ldg(Yp + fi), cz = __ldg(Zp + fi);
    float cn = __fadd_rn(__fadd_rn(__fmul_rn(cx,cx), __fmul_rn(cy,cy)), __fmul_rn(cz,cz));
    if (lane == 0) out[b * 3 * SS + 0 * SS + s] = cx;
    if (lane == 1) out[b * 3 * SS + 1 * SS + s] = cy;
    if (lane == 2) out[b * 3 * SS + 2 * SS + s] = cz;

    const float R2 = 0.01f;
    int cnt = 0;
    for (int base = 0; base < NN; base += 32) {
        int j = base + lane;
        float pxv = __ldg(Xp + j), pyv = __ldg(Yp + j), pzv = __ldg(Zp + j);
        float pn  = __fadd_rn(__fadd_rn(__fmul_rn(pxv,pxv), __fmul_rn(pyv,pyv)), __fmul_rn(pzv,pzv));
        float dot = __fadd_rn(__fadd_rn(__fmul_rn(cx,pxv), __fmul_rn(cy,pyv)), __fmul_rn(cz,pzv));
        float sqr = __fsub_rn(__fadd_rn(cn, pn), __fmul_rn(2.0f, dot));
        bool in = (sqr <= R2);
        unsigned mask = __ballot_sync(0xffffffffu, in);
        int pre = __popc(mask & ((1u << lane) - 1u));
        int slot = cnt + pre;
        if (in && slot < 32) snb[w][slot] = j;
        cnt += __popc(mask);
        if (cnt >= 32) break;
    }
    __syncwarp();
    int j0 = snb[w][0];
    if (lane >= cnt) snb[w][lane] = j0;
    __syncwarp();
    int j = snb[w][lane];

    size_t mbase = (size_t)cid * 32 + lane;
    float gx = __ldg(Xp + j), gy = __ldg(Yp + j), gz = __ldg(Zp + j);
    g_X[(size_t)0 * MM + mbase] = __fsub_rn(gx, cx);
    g_X[(size_t)1 * MM + mbase] = __fsub_rn(gy, cy);
    g_X[(size_t)2 * MM + mbase] = __fsub_rn(gz, cz);
    const float* pb = points + (size_t)b * DD * NN;
    for (int d = 0; d < DD; d++)
        g_X[(size_t)(3 + d) * MM + mbase] = __ldg(pb + d * NN + j);
}

// ---------- fused conv: 256 threads, 2 rows x 8 col-pairs per thread (best: R7) ----------
// MODE 0: in = A ; MODE 1: in = relu(scA*A+shA) ;
// MODE 2: in = relu(scA*A+shA + relu(scB*B2+shB)), also stored to actOut.
template<int CINt, int MODE>
__global__ void __launch_bounds__(256) conv_kernel(
    const float* __restrict__ W,
    const float* __restrict__ A, const float* __restrict__ B2,
    const float* __restrict__ scA, const float* __restrict__ shA,
    const float* __restrict__ scB, const float* __restrict__ shB,
    float* __restrict__ outp, float* __restrict__ actOut,
    double* __restrict__ stS, double* __restrict__ stQ)
{
    extern __shared__ float smem[];
    float* Ws = smem;               // [k][o] : CINt*64 floats
    float* Xs = smem + CINt * 64;   // [k][col] : CINt*128 floats
    int tid = threadIdx.x;
    int m0 = blockIdx.x * 128;

    for (int i = tid; i < 64 * CINt; i += 256) {
        int o = i & 63, k = i >> 6;
        Ws[k * 64 + o] = __ldg(W + o * CINt + k);
    }
    for (int i = tid; i < CINt * 32; i += 256) {
        int k = i >> 5, c = (i & 31) << 2;
        float4 v = *(const float4*)(A + (size_t)k * MM + m0 + c);
        if (MODE == 1) {
            float sc = scA[k], sh = shA[k];
            v.x = fmaxf(fmaf(sc, v.x, sh), 0.f);
            v.y = fmaxf(fmaf(sc, v.y, sh), 0.f);
            v.z = fmaxf(fmaf(sc, v.z, sh), 0.f);
            v.w = fmaxf(fmaf(sc, v.w, sh), 0.f);
        } else if (MODE == 2) {
            float sc = scA[k], sh = shA[k];
            float sb2 = scB[k], s2 = shB[k];
            float4 u = *(const float4*)(B2 + (size_t)k * MM + m0 + c);
            v.x = fmaxf(fmaf(sc, v.x, sh) + fmaxf(fmaf(sb2, u.x, s2), 0.f), 0.f);
            v.y = fmaxf(fmaf(sc, v.y, sh) + fmaxf(fmaf(sb2, u.y, s2), 0.f), 0.f);
            v.z = fmaxf(fmaf(sc, v.z, sh) + fmaxf(fmaf(sb2, u.z, s2), 0.f), 0.f);
            v.w = fmaxf(fmaf(sc, v.w, sh) + fmaxf(fmaf(sb2, u.w, s2), 0.f), 0.f);
            *(float4*)(actOut + (size_t)k * MM + m0 + c) = v;
        }
        *(float4*)(Xs + k * 128 + c) = v;
    }
    __syncthreads();

    int tc = tid & 7, tr = tid >> 3;     // tc: 8 col-pairs (j*8+tc), tr: 2 rows (tr*2+r)
    unsigned long long acc[2][8];
#pragma unroll
    for (int r = 0; r < 2; r++)
#pragma unroll
        for (int j = 0; j < 8; j++) acc[r][j] = 0ull;

    const unsigned long long* Xq = (const unsigned long long*)Xs;
#pragma unroll 4
    for (int k = 0; k < CINt; k++) {
        float2 wv = *(const float2*)(Ws + k * 64 + tr * 2);   // broadcast LDS.64
        unsigned long long w0 = pack2(wv.x, wv.x);
        unsigned long long w1 = pack2(wv.y, wv.y);
        unsigned long long x[8];
#pragma unroll
        for (int j = 0; j < 8; j++) x[j] = Xq[k * 64 + j * 8 + tc];  // conflict-free
#pragma unroll
        for (int j = 0; j < 8; j++) {
            fma2(acc[0][j], w0, x[j]);
            fma2(acc[1][j], w1, x[j]);
        }
    }

#pragma unroll
    for (int r = 0; r < 2; r++) {
        int o = tr * 2 + r;
        unsigned long long* orow = (unsigned long long*)(outp + (size_t)o * MM + m0);
        float s = 0.f, sq = 0.f;
#pragma unroll
        for (int j = 0; j < 8; j++) {
            orow[j * 8 + tc] = acc[r][j];
            float f0, f1; unpack2(acc[r][j], f0, f1);
            s += f0 + f1; sq += f0 * f0 + f1 * f1;
        }
#pragma unroll
        for (int off = 4; off > 0; off >>= 1) {
            s  += __shfl_xor_sync(0xffffffffu, s, off);
            sq += __shfl_xor_sync(0xffffffffu, sq, off);
        }
        if (tc == 0) {
            atomicAdd(stS + o, (double)s);
            atomicAdd(stQ + o, (double)sq);
        }
    }
}

__global__ void bn_finalize_kernel(int bnIdx, const float* __restrict__ g,
                                   const float* __restrict__ b)
{
    int c = threadIdx.x;
    double sum = g_stats[bnIdx * 128 + c];
    double sq  = g_stats[bnIdx * 128 + 64 + c];
    double mean = sum * (1.0 / (double)MM);
    double var  = sq * (1.0 / (double)MM) - mean * mean;
    double inv  = 1.0 / sqrt(var + 1e-5);
    double sc   = (double)g[c] * inv;
    g_scale[bnIdx * 64 + c] = (float)sc;
    g_shift[bnIdx * 64 + c] = (float)((double)b[c] - mean * sc);
}

__global__ void __launch_bounds__(256) finalmax_kernel(float* __restrict__ out) {
    int gid = blockIdx.x * 256 + threadIdx.x;  // b*131072 + o*2048 + s
    int b = gid >> 17;
    int o = (gid >> 11) & 63;
    int s = gid & 2047;
    size_t m = (size_t)(b * SS + s) * KK;
    const float* vp = g_V + (size_t)o * MM + m;
    const float* ap = g_A + (size_t)o * MM + m;
    float sc = g_scale[4 * 64 + o], sh = g_shift[4 * 64 + o];
    float mx = 0.f;
#pragma unroll
    for (int kk = 0; kk < 8; kk++) {
        float4 v = *(const float4*)(vp + kk * 4);
        float4 a = *(const float4*)(ap + kk * 4);
        mx = fmaxf(mx, fmaxf(fmaf(sc, v.x, sh) + a.x, 0.f));
        mx = fmaxf(mx, fmaxf(fmaf(sc, v.y, sh) + a.y, 0.f));
        mx = fmaxf(mx, fmaxf(fmaf(sc, v.z, sh) + a.z, 0.f));
        mx = fmaxf(mx, fmaxf(fmaf(sc, v.w, sh) + a.w, 0.f));
    }
    out[NEWXYZ_SIZE + gid] = mx;
}

extern "C" void kernel_launch(void* const* d_in, const int* in_sizes, int n_in,
                              void* d_out, int out_size)
{
    const float* xyz    = (const float*)d_in[0];
    const float* points = (const float*)d_in[1];
    const float* proj_w = (const float*)d_in[2];
    const float* proj_g = (const float*)d_in[3];
    const float* proj_b = (const float*)d_in[4];
    const float* w1     = (const float*)d_in[5];
    const float* g1     = (const float*)d_in[6];
    const float* b1     = (const float*)d_in[7];
    const float* w2     = (const float*)d_in[8];
    const float* g2     = (const float*)d_in[9];
    const float* b2     = (const float*)d_in[10];
    float* out = (float*)d_out;

    float *pX, *pP, *pU, *pV, *pA, *pSc, *pSh;
    double* pSt;
    cudaGetSymbolAddress((void**)&pX, g_X);
    cudaGetSymbolAddress((void**)&pP, g_P);
    cudaGetSymbolAddress((void**)&pU, g_U);
    cudaGetSymbolAddress((void**)&pV, g_V);
    cudaGetSymbolAddress((void**)&pA, g_A);
    cudaGetSymbolAddress((void**)&pSt, g_stats);
    cudaGetSymbolAddress((void**)&pSc, g_scale);
    cudaGetSymbolAddress((void**)&pSh, g_shift);

    const int FPS_SMEM = 3 * NN * 4 + 128;   // 96 KB xyz + reduce slots
    cudaFuncSetAttribute((const void*)fps_kernel,
                         cudaFuncAttributeMaxDynamicSharedMemorySize, FPS_SMEM);
    cudaFuncSetAttribute((const void*)conv_kernel<32,0>,
                         cudaFuncAttributeMaxDynamicSharedMemorySize, 49152);
    cudaFuncSetAttribute((const void*)conv_kernel<64,1>,
                         cudaFuncAttributeMaxDynamicSharedMemorySize, 49152);
    cudaFuncSetAttribute((const void*)conv_kernel<64,2>,
                         cudaFuncAttributeMaxDynamicSharedMemorySize, 49152);

    zero_stats_kernel<<<1, 64>>>();
    fps_kernel<<<BB, 256, FPS_SMEM>>>(xyz);
    ballgather_kernel<<<(BB * SS) / 8, 256>>>(xyz, points, out);

    // proj conv: P = proj_w * X (raw), stats bn0
    conv_kernel<32,0><<<MM/128, 256, 32*64*4 + 32*128*4>>>(proj_w, pX, nullptr,
        nullptr, nullptr, nullptr, nullptr, pP, nullptr, pSt + 0, pSt + 64);
    bn_finalize_kernel<<<1, 64>>>(0, proj_g, proj_b);

    // depth 0: U = w1[0] * relu(bn0(P)), stats bn1
    conv_kernel<64,1><<<MM/128, 256, 64*64*4 + 64*128*4>>>(w1, pP, nullptr,
        pSc + 0, pSh + 0, nullptr, nullptr, pU, nullptr, pSt + 128, pSt + 192);
    bn_finalize_kernel<<<1, 64>>>(1, g1, b1);

    // V = w2[0] * relu(bn1(U)), stats bn2
    conv_kernel<64,1><<<MM/128, 256, 64*64*4 + 64*128*4>>>(w2, pU, nullptr,
        pSc + 64, pSh + 64, nullptr, nullptr, pV, nullptr, pSt + 256, pSt + 320);
    bn_finalize_kernel<<<1, 64>>>(2, g2, b2);

    // depth 1: x1 = relu(bn2(V) + relu(bn0(P))) -> g_A ; U = w1[1] * x1, stats bn3
    conv_kernel<64,2><<<MM/128, 256, 64*64*4 + 64*128*4>>>(w1 + 64*64, pV, pP,
        pSc + 128, pSh + 128, pSc + 0, pSh + 0, pU, pA, pSt + 384, pSt + 448);
    bn_finalize_kernel<<<1, 64>>>(3, g1 + 64, b1 + 64);

    // V = w2[1] * relu(bn3(U)), stats bn4
    conv_kernel<64,1><<<MM/128, 256, 64*64*4 + 64*128*4>>>(w2 + 64*64, pU, nullptr,
        pSc + 192, pSh + 192, nullptr, nullptr, pV, nullptr, pSt + 512, pSt + 576);
    bn_finalize_kernel<<<1, 64>>>(4, g2 + 64, b2 + 64);

    // feat = max_k relu(bn4(V) + x1)
    finalmax_kernel<<<(BB * 64 * SS) / 256, 256>>>(out);
}

// round 13
// speedup vs baseline: 1.3120x; 1.1024x over previous
#include <cuda_runtime.h>
#include <math.h>

#define BB 4
#define NN 8192
#define SS 2048
#define KK 32
#define DD 29
#define MM (BB*SS*KK)
#define NEWXYZ_SIZE (BB*3*SS)

__device__ float g_X[32 * MM];
__device__ float g_P[64 * MM];
__device__ float g_U[64 * MM];
__device__ float g_V[64 * MM];
__device__ float g_A[64 * MM];
__device__ int    g_fidx[BB * SS];
__device__ double g_stats[5 * 128];
__device__ float  g_scale[5 * 64];
__device__ float  g_shift[5 * 64];

// ---------- packed f32x2 helpers ----------
__device__ __forceinline__ unsigned long long pack2(float lo, float hi) {
    unsigned long long r;
    asm("mov.b64 %0,{%1,%2};" : "=l"(r) : "f"(lo), "f"(hi));
    return r;
}
__device__ __forceinline__ void unpack2(unsigned long long v, float& lo, float& hi) {
    asm("mov.b64 {%0,%1},%2;" : "=f"(lo), "=f"(hi) : "l"(v));
}
__device__ __forceinline__ unsigned long long add2(unsigned long long a, unsigned long long b) {
    unsigned long long r;
    asm("add.rn.f32x2 %0,%1,%2;" : "=l"(r) : "l"(a), "l"(b));
    return r;
}
__device__ __forceinline__ unsigned long long mul2_(unsigned long long a, unsigned long long b) {
    unsigned long long r;
    asm("mul.rn.f32x2 %0,%1,%2;" : "=l"(r) : "l"(a), "l"(b));
    return r;
}
__device__ __forceinline__ void fma2(unsigned long long& acc,
                                     unsigned long long a, unsigned long long bv) {
    asm("fma.rn.f32x2 %0, %1, %2, %0;" : "+l"(acc) : "l"(a), "l"(bv));
}
__device__ __forceinline__ unsigned smem_addr(const void* p) {
    unsigned a;
    asm("{.reg .u64 t; cvta.to.shared.u64 t, %1; cvt.u32.u64 %0, t;}" : "=r"(a) : "l"(p));
    return a;
}

__global__ void zero_stats_kernel() {
    int t = threadIdx.x;
    for (int i = t; i < 5 * 128; i += 64) g_stats[i] = 0.0;
}

// ---------- FPS: 2-CTA cluster per batch; each CTA owns 4096 points ----------
// Key exchange: 45-bit key = (maxbits<<13) | (8191-idx); 3-bit tag in [63:61].
__global__ void __cluster_dims__(2,1,1) __launch_bounds__(256)
fps_kernel(const float* __restrict__ xyz) {
    extern __shared__ float fsm[];
    float* sx = fsm;
    float* sy = fsm + NN;
    float* sz = fsm + 2 * NN;
    unsigned* sb = (unsigned*)(fsm + 3 * NN);                 // [2][8]
    unsigned* si = sb + 16;                                   // [2][8]
    unsigned long long* mb = (unsigned long long*)(sb + 32);  // 2 parity slots

    unsigned rank;
    asm("mov.u32 %0, %%cluster_ctarank;" : "=r"(rank));
    int b = blockIdx.x >> 1;
    const float* Xp = xyz + b * 3 * NN;
    const float* Yp = Xp + NN;
    const float* Zp = Xp + 2 * NN;
    int tid = threadIdx.x, lane = tid & 31, wid = tid >> 5;
    int half = (int)rank * 4096;

    // stage full xyz (for centroid lookup from any index)
    for (int i = tid; i < NN; i += 256) {
        sx[i] = Xp[i]; sy[i] = Yp[i]; sz[i] = Zp[i];
    }
    if (tid < 2) mb[tid] = 0ull;

    // own half: 16 points per thread (8 packed)
    unsigned long long Px[8], Py[8], Pz[8];
    float dist[16];
#pragma unroll
    for (int q = 0; q < 8; q++) {
        int n0 = half + (2 * q) * 256 + tid, n1 = n0 + 256;
        Px[q] = pack2(Xp[n0], Xp[n1]);
        Py[q] = pack2(Yp[n0], Yp[n1]);
        Pz[q] = pack2(Zp[n0], Zp[n1]);
        dist[2 * q] = 1e10f; dist[2 * q + 1] = 1e10f;
    }
    unsigned mbAddr = smem_addr(mb);
    __syncthreads();
    asm volatile("barrier.cluster.arrive.aligned;" ::: "memory");
    asm volatile("barrier.cluster.wait.aligned;" ::: "memory");

    int far = 0;
    for (int it = 0; it < SS; it++) {
        if (rank == 0 && tid == 0) g_fidx[b * SS + it] = far;
        float cx = sx[far], cy = sy[far], cz = sz[far];
        unsigned long long nc_x = pack2(-cx, -cx);
        unsigned long long nc_y = pack2(-cy, -cy);
        unsigned long long nc_z = pack2(-cz, -cz);

        unsigned bbits = 0u, bidx = 0u;
#pragma unroll
        for (int q = 0; q < 8; q++) {
            unsigned long long ax = add2(Px[q], nc_x);
            unsigned long long ay = add2(Py[q], nc_y);
            unsigned long long az = add2(Pz[q], nc_z);
            unsigned long long s  = add2(mul2_(ax, ax), mul2_(ay, ay));
            unsigned long long dd = add2(s, mul2_(az, az));
            float d0, d1; unpack2(dd, d0, d1);
            float nd0 = fminf(dist[2 * q], d0); dist[2 * q] = nd0;
            float nd1 = fminf(dist[2 * q + 1], d1); dist[2 * q + 1] = nd1;
            unsigned u0 = __float_as_uint(nd0);
            if (u0 > bbits) { bbits = u0; bidx = (unsigned)(half + (2 * q) * 256 + tid); }
            unsigned u1 = __float_as_uint(nd1);
            if (u1 > bbits) { bbits = u1; bidx = (unsigned)(half + (2 * q + 1) * 256 + tid); }
        }
        // warp argmax (first-max tie break)
        unsigned wmax = __reduce_max_sync(0xffffffffu, bbits);
        unsigned cand = (bbits == wmax) ? bidx : 0xffffffffu;
        unsigned wmin = __reduce_min_sync(0xffffffffu, cand);
        int p = it & 1;
        if (lane == 0) { sb[p * 8 + wid] = wmax; si[p * 8 + wid] = wmin; }
        __syncthreads();
        unsigned vb = (lane < 8) ? sb[p * 8 + lane] : 0u;
        unsigned vi = (lane < 8) ? si[p * 8 + lane] : 0xffffffffu;
        unsigned gmax = __reduce_max_sync(0xffffffffu, vb);
        unsigned c2 = (vb == gmax) ? vi : 0xffffffffu;
        unsigned farl = __reduce_min_sync(0xffffffffu, c2);

        unsigned long long kl = (((unsigned long long)gmax) << 13)
                              | (unsigned long long)(8191u - farl);
        unsigned exp = ((unsigned)(it >> 1) + 1u) & 7u;
        unsigned slotAddr = mbAddr + (unsigned)(p * 8);
        if (tid == 0) {
            unsigned rem;
            asm("mapa.shared::cluster.u32 %0, %1, %2;"
                : "=r"(rem) : "r"(slotAddr), "r"(rank ^ 1u));
            unsigned long long tagged = (((unsigned long long)exp) << 61) | kl;
            asm volatile("st.shared::cluster.u64 [%0], %1;"
                         :: "r"(rem), "l"(tagged) : "memory");
        }
        unsigned long long v;
        do {
            asm volatile("ld.volatile.shared.u64 %0, [%1];" : "=l"(v) : "r"(slotAddr));
        } while ((unsigned)(v >> 61) != exp);
        unsigned long long kr = v & ((1ull << 61) - 1ull);
        unsigned long long kb = (kl > kr) ? kl : kr;
        far = 8191 - (int)(kb & 0x1FFFull);
    }
    asm volatile("barrier.cluster.arrive.aligned;" ::: "memory");
    asm volatile("barrier.cluster.wait.aligned;" ::: "memory");
}

// ---------- ball query + gather ----------
__global__ void __launch_bounds__(256) ballgather_kernel(
    const float* __restrict__ xyz, const float* __restrict__ points,
    float* __restrict__ out)
{
    __shared__ int snb[8][32];
    int tid = threadIdx.x, lane = tid & 31, w = tid >> 5;
    int cid = blockIdx.x * 8 + w;
    int b = cid >> 11, s = cid & 2047;

    const float* Xp = xyz + b * 3 * NN;
    const float* Yp = Xp + NN;
    const float* Zp = Xp + 2 * NN;

    int fi = g_fidx[b * SS + s];
    float cx = __ldg(Xp + fi), cy = __ldg(Yp + fi), cz = __ldg(Zp + fi);
    float cn = __fadd_rn(__fadd_rn(__fmul_rn(cx,cx), __fmul_rn(cy,cy)), __fmul_rn(cz,cz));
    if (lane == 0) out[b * 3 * SS + 0 * SS + s] = cx;
    if (lane == 1) out[b * 3 * SS + 1 * SS + s] = cy;
    if (lane == 2) out[b * 3 * SS + 2 * SS + s] = cz;

    const float R2 = 0.01f;
    int cnt = 0;
    for (int base = 0; base < NN; base += 32) {
        int j = base + lane;
        float pxv = __ldg(Xp + j), pyv = __ldg(Yp + j), pzv = __ldg(Zp + j);
        float pn  = __fadd_rn(__fadd_rn(__fmul_rn(pxv,pxv), __fmul_rn(pyv,pyv)), __fmul_rn(pzv,pzv));
        float dot = __fadd_rn(__fadd_rn(__fmul_rn(cx,pxv), __fmul_rn(cy,pyv)), __fmul_rn(cz,pzv));
        float sqr = __fsub_rn(__fadd_rn(cn, pn), __fmul_rn(2.0f, dot));
        bool in = (sqr <= R2);
        unsigned mask = __ballot_sync(0xffffffffu, in);
        int pre = __popc(mask & ((1u << lane) - 1u));
        int slot = cnt + pre;
        if (in && slot < 32) snb[w][slot] = j;
        cnt += __popc(mask);
        if (cnt >= 32) break;
    }
    __syncwarp();
    int j0 = snb[w][0];
    if (lane >= cnt) snb[w][lane] = j0;
    __syncwarp();
    int j = snb[w][lane];

    size_t mbase = (size_t)cid * 32 + lane;
    float gx = __ldg(Xp + j), gy = __ldg(Yp + j), gz = __ldg(Zp + j);
    g_X[(size_t)0 * MM + mbase] = __fsub_rn(gx, cx);
    g_X[(size_t)1 * MM + mbase] = __fsub_rn(gy, cy);
    g_X[(size_t)2 * MM + mbase] = __fsub_rn(gz, cz);
    const float* pb = points + (size_t)b * DD * NN;
    for (int d = 0; d < DD; d++)
        g_X[(size_t)(3 + d) * MM + mbase] = __ldg(pb + d * NN + j);
}

// ---------- fused conv: 256 threads, 2 rows x 8 col-pairs per thread ----------
// MODE 0: in = A ; MODE 1: in = relu(scA*A+shA) ;
// MODE 2: in = relu(scA*A+shA + relu(scB*B2+shB)), also stored to actOut.
template<int CINt, int MODE>
__global__ void __launch_bounds__(256) conv_kernel(
    const float* __restrict__ W,
    const float* __restrict__ A, const float* __restrict__ B2,
    const float* __restrict__ scA, const float* __restrict__ shA,
    const float* __restrict__ scB, const float* __restrict__ shB,
    float* __restrict__ outp, float* __restrict__ actOut,
    double* __restrict__ stS, double* __restrict__ stQ)
{
    extern __shared__ float smem[];
    float* Ws = smem;               // [k][o] : CINt*64 floats
    float* Xs = smem + CINt * 64;   // [k][col] : CINt*128 floats
    int tid = threadIdx.x;
    int m0 = blockIdx.x * 128;

    for (int i = tid; i < 64 * CINt; i += 256) {
        int o = i & 63, k = i >> 6;
        Ws[k * 64 + o] = __ldg(W + o * CINt + k);
    }
    for (int i = tid; i < CINt * 32; i += 256) {
        int k = i >> 5, c = (i & 31) << 2;
        float4 v = *(const float4*)(A + (size_t)k * MM + m0 + c);
        if (MODE == 1) {
            float sc = scA[k], sh = shA[k];
            v.x = fmaxf(fmaf(sc, v.x, sh), 0.f);
            v.y = fmaxf(fmaf(sc, v.y, sh), 0.f);
            v.z = fmaxf(fmaf(sc, v.z, sh), 0.f);
            v.w = fmaxf(fmaf(sc, v.w, sh), 0.f);
        } else if (MODE == 2) {
            float sc = scA[k], sh = shA[k];
            float sb2 = scB[k], s2 = shB[k];
            float4 u = *(const float4*)(B2 + (size_t)k * MM + m0 + c);
            v.x = fmaxf(fmaf(sc, v.x, sh) + fmaxf(fmaf(sb2, u.x, s2), 0.f), 0.f);
            v.y = fmaxf(fmaf(sc, v.y, sh) + fmaxf(fmaf(sb2, u.y, s2), 0.f), 0.f);
            v.z = fmaxf(fmaf(sc, v.z, sh) + fmaxf(fmaf(sb2, u.z, s2), 0.f), 0.f);
            v.w = fmaxf(fmaf(sc, v.w, sh) + fmaxf(fmaf(sb2, u.w, s2), 0.f), 0.f);
            *(float4*)(actOut + (size_t)k * MM + m0 + c) = v;
        }
        *(float4*)(Xs + k * 128 + c) = v;
    }
    __syncthreads();

    int tc = tid & 7, tr = tid >> 3;     // tc: 8 col-pairs (j*8+tc), tr: 2 rows (tr*2+r)
    unsigned long long acc[2][8];
#pragma unroll
    for (int r = 0; r < 2; r++)
#pragma unroll
        for (int j = 0; j < 8; j++) acc[r][j] = 0ull;

    const unsigned long long* Xq = (const unsigned long long*)Xs;
#pragma unroll 4
    for (int k = 0; k < CINt; k++) {
        float2 wv = *(const float2*)(Ws + k * 64 + tr * 2);   // broadcast LDS.64
        unsigned long long w0 = pack2(wv.x, wv.x);
        unsigned long long w1 = pack2(wv.y, wv.y);
        unsigned long long x[8];
#pragma unroll
        for (int j = 0; j < 8; j++) x[j] = Xq[k * 64 + j * 8 + tc];  // conflict-free
#pragma unroll
        for (int j = 0; j < 8; j++) {
            fma2(acc[0][j], w0, x[j]);
            fma2(acc[1][j], w1, x[j]);
        }
    }

#pragma unroll
    for (int r = 0; r < 2; r++) {
        int o = tr * 2 + r;
        unsigned long long* orow = (unsigned long long*)(outp + (size_t)o * MM + m0);
        float s = 0.f, sq = 0.f;
#pragma unroll
        for (int j = 0; j < 8; j++) {
            orow[j * 8 + tc] = acc[r][j];
            float f0, f1; unpack2(acc[r][j], f0, f1);
            s += f0 + f1; sq += f0 * f0 + f1 * f1;
        }
#pragma unroll
        for (int off = 4; off > 0; off >>= 1) {
            s  += __shfl_xor_sync(0xffffffffu, s, off);
            sq += __shfl_xor_sync(0xffffffffu, sq, off);
        }
        if (tc == 0) {
            atomicAdd(stS + o, (double)s);
            atomicAdd(stQ + o, (double)sq);
        }
    }
}

__global__ void bn_finalize_kernel(int bnIdx, const float* __restrict__ g,
                                   const float* __restrict__ b)
{
    int c = threadIdx.x;
    double sum = g_stats[bnIdx * 128 + c];
    double sq  = g_stats[bnIdx * 128 + 64 + c];
    double mean = sum * (1.0 / (double)MM);
    double var  = sq * (1.0 / (double)MM) - mean * mean;
    double inv  = 1.0 / sqrt(var + 1e-5);
    double sc   = (double)g[c] * inv;
    g_scale[bnIdx * 64 + c] = (float)sc;
    g_shift[bnIdx * 64 + c] = (float)((double)b[c] - mean * sc);
}

__global__ void __launch_bounds__(256) finalmax_kernel(float* __restrict__ out) {
    int gid = blockIdx.x * 256 + threadIdx.x;  // b*131072 + o*2048 + s
    int b = gid >> 17;
    int o = (gid >> 11) & 63;
    int s = gid & 2047;
    size_t m = (size_t)(b * SS + s) * KK;
    const float* vp = g_V + (size_t)o * MM + m;
    const float* ap = g_A + (size_t)o * MM + m;
    float sc = g_scale[4 * 64 + o], sh = g_shift[4 * 64 + o];
    float mx = 0.f;
#pragma unroll
    for (int kk = 0; kk < 8; kk++) {
        float4 v = *(const float4*)(vp + kk * 4);
        float4 a = *(const float4*)(ap + kk * 4);
        mx = fmaxf(mx, fmaxf(fmaf(sc, v.x, sh) + a.x, 0.f));
        mx = fmaxf(mx, fmaxf(fmaf(sc, v.y, sh) + a.y, 0.f));
        mx = fmaxf(mx, fmaxf(fmaf(sc, v.z, sh) + a.z, 0.f));
        mx = fmaxf(mx, fmaxf(fmaf(sc, v.w, sh) + a.w, 0.f));
    }
    out[NEWXYZ_SIZE + gid] = mx;
}

extern "C" void kernel_launch(void* const* d_in, const int* in_sizes, int n_in,
                              void* d_out, int out_size)
{
    const float* xyz    = (const float*)d_in[0];
    const float* points = (const float*)d_in[1];
    const float* proj_w = (const float*)d_in[2];
    const float* proj_g = (const float*)d_in[3];
    const float* proj_b = (const float*)d_in[4];
    const float* w1     = (const float*)d_in[5];
    const float* g1     = (const float*)d_in[6];
    const float* b1     = (const float*)d_in[7];
    const float* w2     = (const float*)d_in[8];
    const float* g2     = (const float*)d_in[9];
    const float* b2     = (const float*)d_in[10];
    float* out = (float*)d_out;

    float *pX, *pP, *pU, *pV, *pA, *pSc, *pSh;
    double* pSt;
    cudaGetSymbolAddress((void**)&pX, g_X);
    cudaGetSymbolAddress((void**)&pP, g_P);
    cudaGetSymbolAddress((void**)&pU, g_U);
    cudaGetSymbolAddress((void**)&pV, g_V);
    cudaGetSymbolAddress((void**)&pA, g_A);
    cudaGetSymbolAddress((void**)&pSt, g_stats);
    cudaGetSymbolAddress((void**)&pSc, g_scale);
    cudaGetSymbolAddress((void**)&pSh, g_shift);

    const int FPS_SMEM = 3 * NN * 4 + 256;   // 96 KB xyz + reduce slots + mailboxes
    cudaFuncSetAttribute((const void*)fps_kernel,
                         cudaFuncAttributeMaxDynamicSharedMemorySize, FPS_SMEM);
    cudaFuncSetAttribute((const void*)conv_kernel<32,0>,
                         cudaFuncAttributeMaxDynamicSharedMemorySize, 49152);
    cudaFuncSetAttribute((const void*)conv_kernel<64,1>,
                         cudaFuncAttributeMaxDynamicSharedMemorySize, 49152);
    cudaFuncSetAttribute((const void*)conv_kernel<64,2>,
                         cudaFuncAttributeMaxDynamicSharedMemorySize, 49152);

    zero_stats_kernel<<<1, 64>>>();
    fps_kernel<<<BB * 2, 256, FPS_SMEM>>>(xyz);
    ballgather_kernel<<<(BB * SS) / 8, 256>>>(xyz, points, out);

    // proj conv: P = proj_w * X (raw), stats bn0
    conv_kernel<32,0><<<MM/128, 256, 32*64*4 + 32*128*4>>>(proj_w, pX, nullptr,
        nullptr, nullptr, nullptr, nullptr, pP, nullptr, pSt + 0, pSt + 64);
    bn_finalize_kernel<<<1, 64>>>(0, proj_g, proj_b);

    // depth 0: U = w1[0] * relu(bn0(P)), stats bn1
    conv_kernel<64,1><<<MM/128, 256, 64*64*4 + 64*128*4>>>(w1, pP, nullptr,
        pSc + 0, pSh + 0, nullptr, nullptr, pU, nullptr, pSt + 128, pSt + 192);
    bn_finalize_kernel<<<1, 64>>>(1, g1, b1);

    // V = w2[0] * relu(bn1(U)), stats bn2
    conv_kernel<64,1><<<MM/128, 256, 64*64*4 + 64*128*4>>>(w2, pU, nullptr,
        pSc + 64, pSh + 64, nullptr, nullptr, pV, nullptr, pSt + 256, pSt + 320);
    bn_finalize_kernel<<<1, 64>>>(2, g2, b2);

    // depth 1: x1 = relu(bn2(V) + relu(bn0(P))) -> g_A ; U = w1[1] * x1, stats bn3
    conv_kernel<64,2><<<MM/128, 256, 64*64*4 + 64*128*4>>>(w1 + 64*64, pV, pP,
        pSc + 128, pSh + 128, pSc + 0, pSh + 0, pU, pA, pSt + 384, pSt + 448);
    bn_finalize_kernel<<<1, 64>>>(3, g1 + 64, b1 + 64);

    // V = w2[1] * relu(bn3(U)), stats bn4
    conv_kernel<64,1><<<MM/128, 256, 64*64*4 + 64*128*4>>>(w2 + 64*64, pU, nullptr,
        pSc + 192, pSh + 192, nullptr, nullptr, pV, nullptr, pSt + 512, pSt + 576);
    bn_finalize_kernel<<<1, 64>>>(4, g2 + 64, b2 + 64);

    // feat = max_k relu(bn4(V) + x1)
    finalmax_kernel<<<(BB * 64 * SS) / 256, 256>>>(out);
}